// round 8
// baseline (speedup 1.0000x reference)
#include <cuda_runtime.h>

#define NB 256
#define XB 256
#define TB 3
#define KB 64
#define AB 193
#define EPSF 1e-9f

#define MAIN_BLOCKS 6528
#define ROWHALF 98304              // 98304*17 = 6528*256
#define TOTAL_BLOCKS (MAIN_BLOCKS + NB)

__device__ float    g_part[TOTAL_BLOCKS];
__device__ unsigned g_count = 0;

// ---------------------------------------------------------------------------
// Fused kernel.
// Main path: vis loads unconditional; xoff loads gated by gt_class, with the
// gate prefetched into SMEM at block start so the gate is NOT in any load's
// dependency chain (the R4-R6 failure mode). Single-log BCE ({0,1} labels).
//  blockIdx <  NB : per-batch lane-geometry losses (loss3, loss4)
//  blockIdx >= NB : elementwise losses (loss0, loss1, loss2), 2 units/thread
// ---------------------------------------------------------------------------
__global__ void __launch_bounds__(256, 8) k_fused(
    const float* __restrict__ pred, const float* __restrict__ gt,
    const float* __restrict__ hcam_arr, const float* __restrict__ ax,
    const float* __restrict__ ay, const float* __restrict__ xstd,
    const float* __restrict__ zstd, float* __restrict__ out)
{
    const int tid  = threadIdx.x;
    const int lane = tid & 31;
    const int wid  = tid >> 5;
    const unsigned FULL = 0xffffffffu;

    __shared__ float s_w8[8];

    float partial = 0.f;

    if (blockIdx.x >= NB) {
        // =============== MAIN PATH: loss0 + loss1 + loss2 ===============
        const int bid = blockIdx.x - NB;
        const int gid = bid * 256 + tid;
        const int row = gid / 17;
        const int j   = gid - row * 17;
        const int a   = row & 3;               // (row+98304)&3 == row&3
        const int k0  = 4 * j - a;

        const int bx1 = row * AB - a + 4 * j;  // 16B-aligned xoff window
        const int bx2 = bx1 + ROWHALF * AB;

        __shared__ float s_gc[34];             // gc for this block's rows (A,B halves)

        // issue unconditional vis loads FIRST (independent of the gate)
        float4 pvA = *reinterpret_cast<const float4*>(pred + bx1 + 128);
        float4 gvA = *reinterpret_cast<const float4*>(gt   + bx1 + 128);
        float4 pvB = *reinterpret_cast<const float4*>(pred + bx2 + 128);
        float4 gvB = *reinterpret_cast<const float4*>(gt   + bx2 + 128);

        // block-level gc prefetch into smem (rows covered: rowbase..rowbase+16)
        const int rowbase = (bid * 256) / 17;
        if (tid < 17) {
            int r = rowbase + tid;
            float gA = 0.f, gB = 0.f;
            if (r < ROWHALF) {
                gA = __ldg(gt + r * AB + 192);
                gB = __ldg(gt + (r + ROWHALF) * AB + 192);
            }
            s_gc[tid]      = gA;
            s_gc[17 + tid] = gB;
        }
        __syncthreads();

        const int loc = row - rowbase;
        const bool l1 = s_gc[loc]      > 0.f;  // gc in {0,1}
        const bool l2 = s_gc[17 + loc] > 0.f;

        // gated xoff loads: gate is smem-resolved, no DRAM dependency
        float4 pxA, gxA, pxB, gxB;
        if (l1) {
            pxA = *reinterpret_cast<const float4*>(pred + bx1);
            gxA = *reinterpret_cast<const float4*>(gt   + bx1);
        }
        if (l2) {
            pxB = *reinterpret_cast<const float4*>(pred + bx2);
            gxB = *reinterpret_cast<const float4*>(gt   + bx2);
        }

        float acc = 0.f;

        {   // ---- unit 1 BCE ----
            float pvs[4] = {pvA.x, pvA.y, pvA.z, pvA.w};
            float gvs[4] = {gvA.x, gvA.y, gvA.z, gvA.w};
#pragma unroll
            for (int i = 0; i < 4; i++) {
                int k = k0 + i;
                float pv = pvs[i];
                bool g1 = gvs[i] > 0.5f;
                float arg = g1 ? (pv + EPSF) : (1.f - pv + EPSF);
                if ((unsigned)k < 64u) {
                    float cf = g1 ? (1.f / 64.f) : ((1.f + EPSF) / 64.f);
                    acc -= cf * __logf(arg);
                } else if (k == 64) {          // class scalar: loss1 (exact)
                    acc -= __logf(arg);
                }
            }
            if (l1) {                          // loss2, gc == 1 exactly
                float pxs[4] = {pxA.x, pxA.y, pxA.z, pxA.w};
                float gxs[4] = {gxA.x, gxA.y, gxA.z, gxA.w};
#pragma unroll
                for (int i = 0; i < 4; i++)
                    if ((unsigned)(k0 + i) < 64u)
                        acc += gvs[i] * fabsf(pxs[i] - gxs[i]);
            }
        }

        {   // ---- unit 2 ----
            float pvs[4] = {pvB.x, pvB.y, pvB.z, pvB.w};
            float gvs[4] = {gvB.x, gvB.y, gvB.z, gvB.w};
#pragma unroll
            for (int i = 0; i < 4; i++) {
                int k = k0 + i;
                float pv = pvs[i];
                bool g1 = gvs[i] > 0.5f;
                float arg = g1 ? (pv + EPSF) : (1.f - pv + EPSF);
                if ((unsigned)k < 64u) {
                    float cf = g1 ? (1.f / 64.f) : ((1.f + EPSF) / 64.f);
                    acc -= cf * __logf(arg);
                } else if (k == 64) {
                    acc -= __logf(arg);
                }
            }
            if (l2) {
                float pxs[4] = {pxB.x, pxB.y, pxB.z, pxB.w};
                float gxs[4] = {gxB.x, gxB.y, gxB.z, gxB.w};
#pragma unroll
                for (int i = 0; i < 4; i++)
                    if ((unsigned)(k0 + i) < 64u)
                        acc += gvs[i] * fabsf(pxs[i] - gxs[i]);
            }
        }

        // warp reduce + cross-warp via smem
#pragma unroll
        for (int o = 16; o > 0; o >>= 1)
            acc += __shfl_xor_sync(FULL, acc, o);
        if (lane == 0) s_w8[wid] = acc;
        __syncthreads();
        if (tid == 0) {
            float s = 0.f;
#pragma unroll
            for (int w = 0; w < 8; w++) s += s_w8[w];
            partial = s;
        }
    } else {
        // =============== LANES PATH: loss3 + loss4 (x5) ===============
        const int n = blockIdx.x;
        __shared__ int   s_sel[XB];
        __shared__ int   s_nsel;
        __shared__ int   s_wcnt[8];
        __shared__ int   s_rowoff[768];
        __shared__ float s_ax[768];
        __shared__ int   s_keep[KB];
        __shared__ int   s_ck[KB];
        __shared__ int   s_ncols;
        __shared__ float s_lw[8], s_lh[8];

        const float* gtn = gt   + (size_t)n * XB * TB * AB;
        const float* prn = pred + (size_t)n * XB * TB * AB;

        // step 1: stable compaction of sel = gt_class[:,t=0] > 0
        {
            int x = tid;
            float gc0 = gtn[(size_t)x * TB * AB + (AB - 1)];
            bool sel = gc0 > 0.f;
            unsigned b = __ballot_sync(FULL, sel);
            if (lane == 0) s_wcnt[wid] = __popc(b);
            __syncthreads();
            int wbase = 0;
#pragma unroll
            for (int w = 0; w < 8; w++) wbase += (w < wid) ? s_wcnt[w] : 0;
            int pos = wbase + __popc(b & ((1u << lane) - 1u));
            if (sel) s_sel[pos] = x;
            if (tid == 255) s_nsel = pos + (sel ? 1 : 0);
            __syncthreads();
        }
        const int nsel  = s_nsel;
        const int nrows = nsel * 3;

        for (int r = tid; r < nrows; r += 256) {
            int q = r / 3, t = r - q * 3;
            int x = s_sel[q];
            s_rowoff[r] = (x * TB + t) * AB;
            s_ax[r]     = ax[x];
        }
        __syncthreads();

        // step 2: keep[k] <=> no vis==0 among selected rows (vis in {0,1},
        // so this is exactly col_sum >= n_rows). Early-exit scan, chunks of 8.
        if (tid < KB) {
            int k = tid;
            bool dead = false;
            for (int r0 = 0; r0 < nrows && !dead; r0 += 8) {
                float mn = 1.f;
#pragma unroll
                for (int u = 0; u < 8; u++) {
                    int r = r0 + u;
                    if (r < nrows) {
                        float v = gtn[s_rowoff[r] + 128 + k];
                        mn = fminf(mn, v);
                    }
                }
                dead = (mn == 0.f);
            }
            s_keep[k] = (!dead || k < 5) ? 1 : 0;
        }
        __syncthreads();
        if (tid == 0) {
            int nc = 0;
            for (int kk = 0; kk < KB; kk++)
                if (s_keep[kk]) s_ck[nc++] = kk;
            s_ncols = nc;
        }
        __syncthreads();

        const int   ncols = s_ncols;   // always >= 5
        const float hcam  = hcam_arr[n];
        const float xstd0 = xstd[0];

        float lwacc = 0.f, lhacc = 0.f;
        const int npairs = nrows - 1;

        if (ncols <= 8) {
            const int sl  = lane & 7;
            const int seg = lane >> 3;
            for (int i0 = wid * 4; i0 < npairs; i0 += 32) {
                int  i      = i0 + seg;
                bool pvalid = i < npairs;
                int  ii     = pvalid ? i : 0;
                int offA = s_rowoff[ii],     offB = s_rowoff[ii + 1];
                float axA = s_ax[ii],        axB  = s_ax[ii + 1];
                const float* pA = prn + offA;
                const float* gA = gtn + offA;
                const float* pB = prn + offB;
                const float* gB = gtn + offB;

                float width0 = fabsf((gB[0] * xstd0 + axB) - (gA[0] * xstd0 + axA));

                bool act = pvalid && (sl < ncols);
                int  c   = s_ck[sl < ncols ? sl : (ncols - 1)];
                float zsd = zstd[c];
                float ZA = pA[KB + c] * zsd;
                float ZB = pB[KB + c] * zsd;
                float sA = 1.f - ZA / hcam;
                float sB = 1.f - ZB / hcam;
                float laneA = sA * (gA[c] * xstd[c] + axA);
                float laneB = sB * (gB[c] * xstd[c] + axB);
                float YA = sA * ay[c];

                float pl = __shfl_up_sync(FULL, laneA, 1, 8);
                float py = __shfl_up_sync(FULL, YA, 1, 8);
                float ddy = YA - py;
                float ddl = laneA - pl;
                float dy  = fabsf(ddy);
                float dxy = sqrtf(ddl * ddl + ddy * ddy);
                float lY = dy, l = dxy;
                float dy1 = __shfl_sync(FULL, dy, 1, 8);
                if (sl == 0) { lY = dy1; l = dy1; }
                float w  = fabsf(laneB - laneA) * lY / (l + EPSF);
                float pw = __shfl_up_sync(FULL, w, 1, 8);
                if (sl == 0) pw = width0;
                if (act) {
                    lwacc += fabsf(w - pw);
                    lhacc += fabsf(ZB - ZA);
                }
            }
        } else {
            for (int i = wid; i < npairs; i += 8) {
                int offA = s_rowoff[i],  offB = s_rowoff[i + 1];
                float axA = s_ax[i],     axB  = s_ax[i + 1];
                const float* pA = prn + offA;
                const float* gA = gtn + offA;
                const float* pB = prn + offB;
                const float* gB = gtn + offB;

                float w_prev_carry = fabsf((gB[0] * xstd0 + axB) - (gA[0] * xstd0 + axA));
                float carry_lane = 0.f, carry_Y = 0.f;

                for (int jb = 0; jb < ncols; jb += 32) {
                    int  jj  = jb + lane;
                    bool act = jj < ncols;
                    int  c   = s_ck[act ? jj : (ncols - 1)];
                    float zsd = zstd[c];
                    float ZA = pA[KB + c] * zsd;
                    float ZB = pB[KB + c] * zsd;
                    float sA = 1.f - ZA / hcam;
                    float sB = 1.f - ZB / hcam;
                    float laneA = sA * (gA[c] * xstd[c] + axA);
                    float laneB = sB * (gB[c] * xstd[c] + axB);
                    float YA = sA * ay[c];

                    float pl = __shfl_up_sync(FULL, laneA, 1);
                    float py = __shfl_up_sync(FULL, YA, 1);
                    if (lane == 0) { pl = carry_lane; py = carry_Y; }
                    float ddy = YA - py;
                    float ddl = laneA - pl;
                    float dy  = fabsf(ddy);
                    float dxy = sqrtf(ddl * ddl + ddy * ddy);
                    float lY = dy, l = dxy;
                    if (jb == 0) {
                        float dy1 = __shfl_sync(FULL, dy, 1);
                        if (lane == 0) { lY = dy1; l = dy1; }
                    }
                    float w  = fabsf(laneB - laneA) * lY / (l + EPSF);
                    float pw = __shfl_up_sync(FULL, w, 1);
                    if (lane == 0) pw = w_prev_carry;
                    if (act) {
                        lwacc += fabsf(w - pw);
                        lhacc += fabsf(ZB - ZA);
                    }
                    carry_lane   = __shfl_sync(FULL, laneA, 31);
                    carry_Y      = __shfl_sync(FULL, YA, 31);
                    w_prev_carry = __shfl_sync(FULL, w, 31);
                }
            }
        }

#pragma unroll
        for (int o = 16; o > 0; o >>= 1) {
            lwacc += __shfl_xor_sync(FULL, lwacc, o);
            lhacc += __shfl_xor_sync(FULL, lhacc, o);
        }
        if (lane == 0) { s_lw[wid] = lwacc; s_lh[wid] = lhacc; }
        __syncthreads();
        if (tid == 0) {
            float lw = 0.f, lh = 0.f;
#pragma unroll
            for (int w = 0; w < 8; w++) { lw += s_lw[w]; lh += s_lh[w]; }
            partial = 5.f * (lw + lh);
        }
    }

    // ---------------- publish partial + last-block final reduction ----------
    __shared__ bool s_last;
    if (tid == 0) {
        g_part[blockIdx.x] = partial;
        __threadfence();
        unsigned old = atomicAdd(&g_count, 1u);
        s_last = (old == TOTAL_BLOCKS - 1);
    }
    __syncthreads();

    if (s_last) {
        __threadfence();
        __shared__ double sd[256];
        double s = 0.0;
        for (int i = tid; i < TOTAL_BLOCKS; i += 256) s += (double)g_part[i];
        sd[tid] = s;
        __syncthreads();
        for (int o = 128; o > 0; o >>= 1) {
            if (tid < o) sd[tid] += sd[tid + o];
            __syncthreads();
        }
        if (tid == 0) {
            out[0] = (float)sd[0];
            g_count = 0;             // reset for next graph replay
        }
    }
}

extern "C" void kernel_launch(void* const* d_in, const int* in_sizes, int n_in,
                              void* d_out, int out_size) {
    const float* pred = (const float*)d_in[0];
    const float* gt   = (const float*)d_in[1];
    const float* hcam = (const float*)d_in[2];
    const float* axs  = (const float*)d_in[3];
    const float* ays  = (const float*)d_in[4];
    const float* xstd = (const float*)d_in[5];
    const float* zstd = (const float*)d_in[6];

    k_fused<<<TOTAL_BLOCKS, 256>>>(pred, gt, hcam, axs, ays, xstd, zstd,
                                   (float*)d_out);
}

// round 9
// speedup vs baseline: 1.1579x; 1.1579x over previous
#include <cuda_runtime.h>

#define NB 256
#define XB 256
#define TB 3
#define KB 64
#define AB 193
#define EPSF 1e-9f

#define ROWQ 49152                 // rows per unit-pass; 4 passes cover 196608
#define MAIN_BLOCKS 3264           // 49152*17/256
#define TOTAL_BLOCKS (MAIN_BLOCKS + NB)

__device__ float    g_part[TOTAL_BLOCKS];
__device__ unsigned g_count = 0;

// ---------------------------------------------------------------------------
// Fused kernel. Main path: 4 units/thread. All gc + vis loads issue as one
// independent front batch; gated xoff loads issue together after one gate
// round-trip (per-thread dependency only -- no barriers, no shared gates).
//  blockIdx <  NB : per-batch lane-geometry losses (loss3, loss4)
//  blockIdx >= NB : elementwise losses (loss0, loss1, loss2)
// ---------------------------------------------------------------------------
__global__ void __launch_bounds__(256, 6) k_fused(
    const float* __restrict__ pred, const float* __restrict__ gt,
    const float* __restrict__ hcam_arr, const float* __restrict__ ax,
    const float* __restrict__ ay, const float* __restrict__ xstd,
    const float* __restrict__ zstd, float* __restrict__ out)
{
    const int tid  = threadIdx.x;
    const int lane = tid & 31;
    const int wid  = tid >> 5;
    const unsigned FULL = 0xffffffffu;

    __shared__ float s_w8[8];

    float partial = 0.f;

    if (blockIdx.x >= NB) {
        // =============== MAIN PATH: loss0 + loss1 + loss2 ===============
        const int gid = (blockIdx.x - NB) * 256 + tid;
        const int row = gid / 17;              // 0..49151
        const int j   = gid - row * 17;
        const int a   = row & 3;               // (row + u*49152)&3 == row&3
        const int k0  = 4 * j - a;

        const int bx0 = row * AB - a + 4 * j;  // 16B-aligned xoff window, unit 0

        // front batch: 4 independent gc loads
        float gcs[4];
#pragma unroll
        for (int u = 0; u < 4; u++)
            gcs[u] = __ldg(gt + (row + u * ROWQ) * AB + 192);

        float acc = 0.f;

#pragma unroll
        for (int u = 0; u < 4; u++) {
            const int bx = bx0 + u * (ROWQ * AB);

            float4 pv4 = *reinterpret_cast<const float4*>(pred + bx + 128);
            float4 gv4 = *reinterpret_cast<const float4*>(gt   + bx + 128);

            const bool lx = gcs[u] > 0.f;      // gc in {0,1}
            float4 px4, gx4;
            if (lx) {
                px4 = *reinterpret_cast<const float4*>(pred + bx);
                gx4 = *reinterpret_cast<const float4*>(gt   + bx);
            }

            float pvs[4] = {pv4.x, pv4.y, pv4.z, pv4.w};
            float gvs[4] = {gv4.x, gv4.y, gv4.z, gv4.w};
#pragma unroll
            for (int i = 0; i < 4; i++) {
                int k = k0 + i;
                float pv = pvs[i];
                bool g1 = gvs[i] > 0.5f;
                float arg = g1 ? (pv + EPSF) : (1.f - pv + EPSF);
                if ((unsigned)k < 64u) {
                    float cf = g1 ? (1.f / 64.f) : ((1.f + EPSF) / 64.f);
                    acc -= cf * __logf(arg);   // loss0 (single-log BCE)
                } else if (k == 64) {
                    acc -= __logf(arg);        // loss1 (class scalar, exact)
                }
            }
            if (lx) {                          // loss2, gc == 1 exactly
                float pxs[4] = {px4.x, px4.y, px4.z, px4.w};
                float gxs[4] = {gx4.x, gx4.y, gx4.z, gx4.w};
#pragma unroll
                for (int i = 0; i < 4; i++)
                    if ((unsigned)(k0 + i) < 64u)
                        acc += gvs[i] * fabsf(pxs[i] - gxs[i]);
            }
        }

        // warp reduce + cross-warp via smem
#pragma unroll
        for (int o = 16; o > 0; o >>= 1)
            acc += __shfl_xor_sync(FULL, acc, o);
        if (lane == 0) s_w8[wid] = acc;
        __syncthreads();
        if (tid == 0) {
            float s = 0.f;
#pragma unroll
            for (int w = 0; w < 8; w++) s += s_w8[w];
            partial = s;
        }
    } else {
        // =============== LANES PATH: loss3 + loss4 (x5) ===============
        const int n = blockIdx.x;
        __shared__ int   s_sel[XB];
        __shared__ int   s_nsel;
        __shared__ int   s_wcnt[8];
        __shared__ int   s_rowoff[768];
        __shared__ float s_ax[768];
        __shared__ int   s_keep[KB];
        __shared__ int   s_ck[KB];
        __shared__ int   s_ncols;
        __shared__ float s_lw[8], s_lh[8];

        const float* gtn = gt   + (size_t)n * XB * TB * AB;
        const float* prn = pred + (size_t)n * XB * TB * AB;

        // step 1: stable compaction of sel = gt_class[:,t=0] > 0
        {
            int x = tid;
            float gc0 = gtn[(size_t)x * TB * AB + (AB - 1)];
            bool sel = gc0 > 0.f;
            unsigned b = __ballot_sync(FULL, sel);
            if (lane == 0) s_wcnt[wid] = __popc(b);
            __syncthreads();
            int wbase = 0;
#pragma unroll
            for (int w = 0; w < 8; w++) wbase += (w < wid) ? s_wcnt[w] : 0;
            int pos = wbase + __popc(b & ((1u << lane) - 1u));
            if (sel) s_sel[pos] = x;
            if (tid == 255) s_nsel = pos + (sel ? 1 : 0);
            __syncthreads();
        }
        const int nsel  = s_nsel;
        const int nrows = nsel * 3;

        for (int r = tid; r < nrows; r += 256) {
            int q = r / 3, t = r - q * 3;
            int x = s_sel[q];
            s_rowoff[r] = (x * TB + t) * AB;
            s_ax[r]     = ax[x];
        }
        __syncthreads();

        // step 2: keep[k] <=> no vis==0 among selected rows (vis in {0,1},
        // exactly col_sum >= n_rows). Early-exit scan in chunks of 8.
        if (tid < KB) {
            int k = tid;
            bool dead = false;
            for (int r0 = 0; r0 < nrows && !dead; r0 += 8) {
                float mn = 1.f;
#pragma unroll
                for (int u = 0; u < 8; u++) {
                    int r = r0 + u;
                    if (r < nrows) {
                        float v = gtn[s_rowoff[r] + 128 + k];
                        mn = fminf(mn, v);
                    }
                }
                dead = (mn == 0.f);
            }
            s_keep[k] = (!dead || k < 5) ? 1 : 0;
        }
        __syncthreads();
        if (tid == 0) {
            int nc = 0;
            for (int kk = 0; kk < KB; kk++)
                if (s_keep[kk]) s_ck[nc++] = kk;
            s_ncols = nc;
        }
        __syncthreads();

        const int   ncols = s_ncols;   // always >= 5
        const float hcam  = hcam_arr[n];
        const float xstd0 = xstd[0];

        float lwacc = 0.f, lhacc = 0.f;
        const int npairs = nrows - 1;

        if (ncols <= 8) {
            const int sl  = lane & 7;
            const int seg = lane >> 3;
            for (int i0 = wid * 4; i0 < npairs; i0 += 32) {
                int  i      = i0 + seg;
                bool pvalid = i < npairs;
                int  ii     = pvalid ? i : 0;
                int offA = s_rowoff[ii],     offB = s_rowoff[ii + 1];
                float axA = s_ax[ii],        axB  = s_ax[ii + 1];
                const float* pA = prn + offA;
                const float* gA = gtn + offA;
                const float* pB = prn + offB;
                const float* gB = gtn + offB;

                float width0 = fabsf((gB[0] * xstd0 + axB) - (gA[0] * xstd0 + axA));

                bool act = pvalid && (sl < ncols);
                int  c   = s_ck[sl < ncols ? sl : (ncols - 1)];
                float zsd = zstd[c];
                float ZA = pA[KB + c] * zsd;
                float ZB = pB[KB + c] * zsd;
                float sA = 1.f - ZA / hcam;
                float sB = 1.f - ZB / hcam;
                float laneA = sA * (gA[c] * xstd[c] + axA);
                float laneB = sB * (gB[c] * xstd[c] + axB);
                float YA = sA * ay[c];

                float pl = __shfl_up_sync(FULL, laneA, 1, 8);
                float py = __shfl_up_sync(FULL, YA, 1, 8);
                float ddy = YA - py;
                float ddl = laneA - pl;
                float dy  = fabsf(ddy);
                float dxy = sqrtf(ddl * ddl + ddy * ddy);
                float lY = dy, l = dxy;
                float dy1 = __shfl_sync(FULL, dy, 1, 8);
                if (sl == 0) { lY = dy1; l = dy1; }
                float w  = fabsf(laneB - laneA) * lY / (l + EPSF);
                float pw = __shfl_up_sync(FULL, w, 1, 8);
                if (sl == 0) pw = width0;
                if (act) {
                    lwacc += fabsf(w - pw);
                    lhacc += fabsf(ZB - ZA);
                }
            }
        } else {
            for (int i = wid; i < npairs; i += 8) {
                int offA = s_rowoff[i],  offB = s_rowoff[i + 1];
                float axA = s_ax[i],     axB  = s_ax[i + 1];
                const float* pA = prn + offA;
                const float* gA = gtn + offA;
                const float* pB = prn + offB;
                const float* gB = gtn + offB;

                float w_prev_carry = fabsf((gB[0] * xstd0 + axB) - (gA[0] * xstd0 + axA));
                float carry_lane = 0.f, carry_Y = 0.f;

                for (int jb = 0; jb < ncols; jb += 32) {
                    int  jj  = jb + lane;
                    bool act = jj < ncols;
                    int  c   = s_ck[act ? jj : (ncols - 1)];
                    float zsd = zstd[c];
                    float ZA = pA[KB + c] * zsd;
                    float ZB = pB[KB + c] * zsd;
                    float sA = 1.f - ZA / hcam;
                    float sB = 1.f - ZB / hcam;
                    float laneA = sA * (gA[c] * xstd[c] + axA);
                    float laneB = sB * (gB[c] * xstd[c] + axB);
                    float YA = sA * ay[c];

                    float pl = __shfl_up_sync(FULL, laneA, 1);
                    float py = __shfl_up_sync(FULL, YA, 1);
                    if (lane == 0) { pl = carry_lane; py = carry_Y; }
                    float ddy = YA - py;
                    float ddl = laneA - pl;
                    float dy  = fabsf(ddy);
                    float dxy = sqrtf(ddl * ddl + ddy * ddy);
                    float lY = dy, l = dxy;
                    if (jb == 0) {
                        float dy1 = __shfl_sync(FULL, dy, 1);
                        if (lane == 0) { lY = dy1; l = dy1; }
                    }
                    float w  = fabsf(laneB - laneA) * lY / (l + EPSF);
                    float pw = __shfl_up_sync(FULL, w, 1);
                    if (lane == 0) pw = w_prev_carry;
                    if (act) {
                        lwacc += fabsf(w - pw);
                        lhacc += fabsf(ZB - ZA);
                    }
                    carry_lane   = __shfl_sync(FULL, laneA, 31);
                    carry_Y      = __shfl_sync(FULL, YA, 31);
                    w_prev_carry = __shfl_sync(FULL, w, 31);
                }
            }
        }

#pragma unroll
        for (int o = 16; o > 0; o >>= 1) {
            lwacc += __shfl_xor_sync(FULL, lwacc, o);
            lhacc += __shfl_xor_sync(FULL, lhacc, o);
        }
        if (lane == 0) { s_lw[wid] = lwacc; s_lh[wid] = lhacc; }
        __syncthreads();
        if (tid == 0) {
            float lw = 0.f, lh = 0.f;
#pragma unroll
            for (int w = 0; w < 8; w++) { lw += s_lw[w]; lh += s_lh[w]; }
            partial = 5.f * (lw + lh);
        }
    }

    // ---------------- publish partial + last-block final reduction ----------
    __shared__ bool s_last;
    if (tid == 0) {
        g_part[blockIdx.x] = partial;
        __threadfence();
        unsigned old = atomicAdd(&g_count, 1u);
        s_last = (old == TOTAL_BLOCKS - 1);
    }
    __syncthreads();

    if (s_last) {
        __threadfence();
        __shared__ double sd[256];
        double s = 0.0;
        for (int i = tid; i < TOTAL_BLOCKS; i += 256) s += (double)g_part[i];
        sd[tid] = s;
        __syncthreads();
        for (int o = 128; o > 0; o >>= 1) {
            if (tid < o) sd[tid] += sd[tid + o];
            __syncthreads();
        }
        if (tid == 0) {
            out[0] = (float)sd[0];
            g_count = 0;             // reset for next graph replay
        }
    }
}

extern "C" void kernel_launch(void* const* d_in, const int* in_sizes, int n_in,
                              void* d_out, int out_size) {
    const float* pred = (const float*)d_in[0];
    const float* gt   = (const float*)d_in[1];
    const float* hcam = (const float*)d_in[2];
    const float* axs  = (const float*)d_in[3];
    const float* ays  = (const float*)d_in[4];
    const float* xstd = (const float*)d_in[5];
    const float* zstd = (const float*)d_in[6];

    k_fused<<<TOTAL_BLOCKS, 256>>>(pred, gt, hcam, axs, ays, xstd, zstd,
                                   (float*)d_out);
}